// round 2
// baseline (speedup 1.0000x reference)
#include <cuda_runtime.h>
#include <math.h>

#define BS 32768
#define NI 128
#define H  640
#define H3 1920
#define NO 256

#define TM 64
#define TN 64
#define BK 16

// ---------------- scratch (device globals; no allocation allowed) ----------------
__device__ float g_h0[BS * H];     // 84 MB
__device__ float g_h1[BS * H];     // 84 MB
__device__ float g_S [BS * NI];    // 16 MB  (per-row node-sum, 128 wide)
__device__ float g_Wd [H3 * H];    // rows 0..1279: Whh - Wih ; rows 1280..1919: Whh (h_n part)
__device__ float g_Win[H * H];     // Wih rows 1280..1919 (i_n part, subtracted)
__device__ float g_Wf [H3 * NI];   // folded Wih: Wf[j][d] = sum_c Wih[j][c*128+d]

// ---------------- weight preprocessing ----------------
__global__ void prep_wd(const float* __restrict__ Wih, const float* __restrict__ Whh) {
    int i = blockIdx.x * blockDim.x + threadIdx.x;
    if (i < H3 * H) {
        int j = i / H;
        float v = Whh[i];
        if (j < 2 * H) v -= Wih[i];
        g_Wd[i] = v;
    }
}
__global__ void prep_win(const float* __restrict__ Wih) {
    int i = blockIdx.x * blockDim.x + threadIdx.x;
    if (i < H * H) g_Win[i] = Wih[2 * H * H + i];
}
__global__ void prep_wf(const float* __restrict__ Wih) {
    int i = blockIdx.x * blockDim.x + threadIdx.x;
    if (i < H3 * NI) {
        int j = i / NI, d = i - j * NI;
        float s = 0.f;
        #pragma unroll
        for (int c = 0; c < 5; c++) s += Wih[j * H + c * NI + d];
        g_Wf[i] = s;
    }
}

// ---------------- embedding gather (+ initial node-sum S) ----------------
__global__ void gather_kernel(const int* __restrict__ feat,
                              const float* __restrict__ e0, const float* __restrict__ e1,
                              const float* __restrict__ e2, const float* __restrict__ e3,
                              const float* __restrict__ e4) {
    int i = blockIdx.x * blockDim.x + threadIdx.x;  // BS*NI threads
    int row = i >> 7, d = i & 127;
    const int* f = feat + row * 5;
    float v0 = e0[(long)f[0] * NI + d];
    float v1 = e1[(long)f[1] * NI + d];
    float v2 = e2[(long)f[2] * NI + d];
    float v3 = e3[(long)f[3] * NI + d];
    float v4 = e4[(long)f[4] * NI + d];
    float* hr = g_h0 + (size_t)row * H;
    hr[0 * NI + d] = v0;
    hr[1 * NI + d] = v1;
    hr[2 * NI + d] = v2;
    hr[3 * NI + d] = v3;
    hr[4 * NI + d] = v4;
    g_S[i] = v0 + v1 + v2 + v3 + v4;
}

// node-sum of g_h1 (between rounds)
__global__ void sum_kernel() {
    int i = blockIdx.x * blockDim.x + threadIdx.x;
    int row = i >> 7, d = i & 127;
    const float* hr = g_h1 + (size_t)row * H;
    g_S[i] = hr[d] + hr[NI + d] + hr[2 * NI + d] + hr[3 * NI + d] + hr[4 * NI + d];
}

// ---------------- fused GRU round: GEMM (4 K=640 + 3 K=128 accumulators) + gates ----------------
__global__ __launch_bounds__(256, 2)
void gru_kernel(int dir, const float* __restrict__ bih, const float* __restrict__ bhh) {
    const float* hin  = dir ? g_h1 : g_h0;
    float*       hout = dir ? g_h0 : g_h1;

    __shared__ __align__(16) float As [BK][TM + 4];
    __shared__ __align__(16) float Brs[BK][TN + 4];
    __shared__ __align__(16) float Bzs[BK][TN + 4];
    __shared__ __align__(16) float Bns[BK][TN + 4];
    __shared__ __align__(16) float Bis[BK][TN + 4];

    int tid = threadIdx.x;
    int tx = tid & 15, ty = tid >> 4;    // 16x16 compute layout, 4x4 microtile
    int lm = tid >> 2, lq = tid & 3;     // loader layout: 64 rows x 4 quads
    int row0 = blockIdx.x * TM;
    int j0   = blockIdx.y * TN;

    float ar[16], az[16], ah[16], ai[16];
    #pragma unroll
    for (int q = 0; q < 16; q++) { ar[q] = 0.f; az[q] = 0.f; ah[q] = 0.f; ai[q] = 0.f; }

    // ---- main loop over K = H (operand: h) ----
    for (int k0 = 0; k0 < H; k0 += BK) {
        float4 v;
        v = *(const float4*)&hin[(size_t)(row0 + lm) * H + k0 + lq * 4];
        As[lq*4+0][lm] = v.x; As[lq*4+1][lm] = v.y; As[lq*4+2][lm] = v.z; As[lq*4+3][lm] = v.w;
        v = *(const float4*)&g_Wd[(size_t)(j0 + lm) * H + k0 + lq * 4];
        Brs[lq*4+0][lm] = v.x; Brs[lq*4+1][lm] = v.y; Brs[lq*4+2][lm] = v.z; Brs[lq*4+3][lm] = v.w;
        v = *(const float4*)&g_Wd[(size_t)(H + j0 + lm) * H + k0 + lq * 4];
        Bzs[lq*4+0][lm] = v.x; Bzs[lq*4+1][lm] = v.y; Bzs[lq*4+2][lm] = v.z; Bzs[lq*4+3][lm] = v.w;
        v = *(const float4*)&g_Wd[(size_t)(2 * H + j0 + lm) * H + k0 + lq * 4];
        Bns[lq*4+0][lm] = v.x; Bns[lq*4+1][lm] = v.y; Bns[lq*4+2][lm] = v.z; Bns[lq*4+3][lm] = v.w;
        v = *(const float4*)&g_Win[(size_t)(j0 + lm) * H + k0 + lq * 4];
        Bis[lq*4+0][lm] = v.x; Bis[lq*4+1][lm] = v.y; Bis[lq*4+2][lm] = v.z; Bis[lq*4+3][lm] = v.w;
        __syncthreads();

        #pragma unroll
        for (int k = 0; k < BK; k++) {
            float4 a  = *(float4*)&As [k][ty * 4];
            float4 br = *(float4*)&Brs[k][tx * 4];
            float4 bz = *(float4*)&Bzs[k][tx * 4];
            float4 bn = *(float4*)&Bns[k][tx * 4];
            float4 bi = *(float4*)&Bis[k][tx * 4];
            float av[4] = {a.x, a.y, a.z, a.w};
            float rv[4] = {br.x, br.y, br.z, br.w};
            float zv[4] = {bz.x, bz.y, bz.z, bz.w};
            float nv[4] = {bn.x, bn.y, bn.z, bn.w};
            float iv[4] = {bi.x, bi.y, bi.z, bi.w};
            #pragma unroll
            for (int i = 0; i < 4; i++)
                #pragma unroll
                for (int jj = 0; jj < 4; jj++) {
                    ar[i*4+jj] += av[i] * rv[jj];
                    az[i*4+jj] += av[i] * zv[jj];
                    ah[i*4+jj] += av[i] * nv[jj];
                    ai[i*4+jj] -= av[i] * iv[jj];   // i_n gets -h·Wih_n
                }
        }
        __syncthreads();
    }

    // ---- S loop over K = NI (operand: per-row node-sum, folded weights) ----
    for (int k0 = 0; k0 < NI; k0 += BK) {
        float4 v;
        v = *(const float4*)&g_S[(size_t)(row0 + lm) * NI + k0 + lq * 4];
        As[lq*4+0][lm] = v.x; As[lq*4+1][lm] = v.y; As[lq*4+2][lm] = v.z; As[lq*4+3][lm] = v.w;
        v = *(const float4*)&g_Wf[(size_t)(j0 + lm) * NI + k0 + lq * 4];
        Brs[lq*4+0][lm] = v.x; Brs[lq*4+1][lm] = v.y; Brs[lq*4+2][lm] = v.z; Brs[lq*4+3][lm] = v.w;
        v = *(const float4*)&g_Wf[(size_t)(H + j0 + lm) * NI + k0 + lq * 4];
        Bzs[lq*4+0][lm] = v.x; Bzs[lq*4+1][lm] = v.y; Bzs[lq*4+2][lm] = v.z; Bzs[lq*4+3][lm] = v.w;
        v = *(const float4*)&g_Wf[(size_t)(2 * H + j0 + lm) * NI + k0 + lq * 4];
        Bis[lq*4+0][lm] = v.x; Bis[lq*4+1][lm] = v.y; Bis[lq*4+2][lm] = v.z; Bis[lq*4+3][lm] = v.w;
        __syncthreads();

        #pragma unroll
        for (int k = 0; k < BK; k++) {
            float4 a  = *(float4*)&As [k][ty * 4];
            float4 br = *(float4*)&Brs[k][tx * 4];
            float4 bz = *(float4*)&Bzs[k][tx * 4];
            float4 bi = *(float4*)&Bis[k][tx * 4];
            float av[4] = {a.x, a.y, a.z, a.w};
            float rv[4] = {br.x, br.y, br.z, br.w};
            float zv[4] = {bz.x, bz.y, bz.z, bz.w};
            float iv[4] = {bi.x, bi.y, bi.z, bi.w};
            #pragma unroll
            for (int i = 0; i < 4; i++)
                #pragma unroll
                for (int jj = 0; jj < 4; jj++) {
                    ar[i*4+jj] += av[i] * rv[jj];
                    az[i*4+jj] += av[i] * zv[jj];
                    ai[i*4+jj] += av[i] * iv[jj];   // i_n gets +S·Wf_n
                }
        }
        __syncthreads();
    }

    // ---- fused GRU gate epilogue ----
    int mbase = row0 + ty * 4;
    #pragma unroll
    for (int jj = 0; jj < 4; jj++) {
        int j = j0 + tx * 4 + jj;
        float brb  = bih[j]         + bhh[j];
        float bzb  = bih[H + j]     + bhh[H + j];
        float bnbi = bih[2 * H + j];
        float bnbh = bhh[2 * H + j];
        #pragma unroll
        for (int i = 0; i < 4; i++) {
            int m = mbase + i;
            float r = 1.f / (1.f + expf(-(ar[i*4+jj] + brb)));
            float z = 1.f / (1.f + expf(-(az[i*4+jj] + bzb)));
            float n = tanhf(ai[i*4+jj] + bnbi + r * (ah[i*4+jj] + bnbh));
            float ho = hin[(size_t)m * H + j];
            hout[(size_t)m * H + j] = (1.f - z) * n + z * ho;
        }
    }
}

// ---------------- final FC: out = h @ Wfc^T + bfc ----------------
__global__ __launch_bounds__(256, 2)
void fc_kernel(const float* __restrict__ Wfc, const float* __restrict__ bfc,
               float* __restrict__ out) {
    __shared__ __align__(16) float As[BK][TM + 4];
    __shared__ __align__(16) float Bs[BK][TN + 4];

    int tid = threadIdx.x;
    int tx = tid & 15, ty = tid >> 4;
    int lm = tid >> 2, lq = tid & 3;
    int row0 = blockIdx.x * TM;
    int j0   = blockIdx.y * TN;

    float acc[16];
    #pragma unroll
    for (int q = 0; q < 16; q++) acc[q] = 0.f;

    for (int k0 = 0; k0 < H; k0 += BK) {
        float4 v;
        v = *(const float4*)&g_h0[(size_t)(row0 + lm) * H + k0 + lq * 4];
        As[lq*4+0][lm] = v.x; As[lq*4+1][lm] = v.y; As[lq*4+2][lm] = v.z; As[lq*4+3][lm] = v.w;
        v = *(const float4*)&Wfc[(size_t)(j0 + lm) * H + k0 + lq * 4];
        Bs[lq*4+0][lm] = v.x; Bs[lq*4+1][lm] = v.y; Bs[lq*4+2][lm] = v.z; Bs[lq*4+3][lm] = v.w;
        __syncthreads();

        #pragma unroll
        for (int k = 0; k < BK; k++) {
            float4 a = *(float4*)&As[k][ty * 4];
            float4 b = *(float4*)&Bs[k][tx * 4];
            float av[4] = {a.x, a.y, a.z, a.w};
            float bv[4] = {b.x, b.y, b.z, b.w};
            #pragma unroll
            for (int i = 0; i < 4; i++)
                #pragma unroll
                for (int jj = 0; jj < 4; jj++)
                    acc[i*4+jj] += av[i] * bv[jj];
        }
        __syncthreads();
    }

    int mbase = row0 + ty * 4;
    #pragma unroll
    for (int jj = 0; jj < 4; jj++) {
        int j = j0 + tx * 4 + jj;
        float bb = bfc[j];
        #pragma unroll
        for (int i = 0; i < 4; i++)
            out[(size_t)(mbase + i) * NO + j] = acc[i*4+jj] + bb;
    }
}

// ---------------- launch ----------------
extern "C" void kernel_launch(void* const* d_in, const int* in_sizes, int n_in,
                              void* d_out, int out_size) {
    const int*   feat = (const int*)  d_in[0];
    const float* e_id = (const float*)d_in[1];
    const float* e_ag = (const float*)d_in[2];
    const float* e_ge = (const float*)d_in[3];
    const float* e_oc = (const float*)d_in[4];
    const float* e_zp = (const float*)d_in[5];
    const float* Wih  = (const float*)d_in[6];
    const float* Whh  = (const float*)d_in[7];
    const float* bih  = (const float*)d_in[8];
    const float* bhh  = (const float*)d_in[9];
    const float* Wfc  = (const float*)d_in[10];
    const float* bfc  = (const float*)d_in[11];
    float* out = (float*)d_out;

    prep_wd <<<(H3 * H  + 255) / 256, 256>>>(Wih, Whh);
    prep_win<<<(H * H   + 255) / 256, 256>>>(Wih);
    prep_wf <<<(H3 * NI + 255) / 256, 256>>>(Wih);

    gather_kernel<<<(BS * NI) / 256, 256>>>(feat, e_id, e_ag, e_ge, e_oc, e_zp);

    dim3 gg(BS / TM, H / TN);
    gru_kernel<<<gg, 256>>>(0, bih, bhh);        // g_h0 -> g_h1
    sum_kernel<<<(BS * NI) / 256, 256>>>();      // S from g_h1
    gru_kernel<<<gg, 256>>>(1, bih, bhh);        // g_h1 -> g_h0

    dim3 gf(BS / TM, NO / TN);
    fc_kernel<<<gf, 256>>>(Wfc, bfc, out);
}

// round 3
// speedup vs baseline: 2.8590x; 2.8590x over previous
#include <cuda_runtime.h>
#include <math.h>
#include <stdint.h>

#define BS 32768
#define NI 128
#define H  640
#define H3 1920
#define NO 256
#define KP 768          // packed K: 640 (h) + 128 (S)

// ---------------- scratch (device globals) ----------------
__device__ float g_A0[BS * KP];            // 100.7 MB: [h | S], tf32-rounded
__device__ float g_A1[BS * KP];            // 100.7 MB
__device__ float g_WB[4 * H * KP];         // 7.9 MB: packed per-gate weights, tf32-rounded

// ---------------- helpers ----------------
__device__ __forceinline__ float tf32r(float x) {
    uint32_t u;
    asm("cvt.rna.tf32.f32 %0, %1;" : "=r"(u) : "f"(x));
    return __uint_as_float(u);
}

__device__ __forceinline__ void mma_tf32(float* c, const uint32_t* a, const uint32_t* b) {
    asm volatile(
        "mma.sync.aligned.m16n8k8.row.col.f32.tf32.tf32.f32 "
        "{%0,%1,%2,%3}, {%4,%5,%6,%7}, {%8,%9}, {%0,%1,%2,%3};"
        : "+f"(c[0]), "+f"(c[1]), "+f"(c[2]), "+f"(c[3])
        : "r"(a[0]), "r"(a[1]), "r"(a[2]), "r"(a[3]), "r"(b[0]), "r"(b[1]));
}

#define CP_ASYNC16(dst_u32, src_ptr) \
    asm volatile("cp.async.cg.shared.global [%0], [%1], 16;\n" :: "r"(dst_u32), "l"(src_ptr))
#define CP_COMMIT() asm volatile("cp.async.commit_group;\n" ::)
#define CP_WAIT1()  asm volatile("cp.async.wait_group 1;\n" ::)
#define CP_WAIT0()  asm volatile("cp.async.wait_group 0;\n" ::)

// ---------------- weight packing ----------------
// g_WB[g][j][k]: gate g in {r, z, n_h, n_i}
//   k <  640: g0: Whh_r - Wih_r ; g1: Whh_z - Wih_z ; g2: Whh_n ; g3: -Wih_n
//   k >= 640 (d = k-640, folded S columns): g0/g1/g3: sum_c Wih_gate[j][c*128+d] ; g2: 0
__global__ void prep_wb(const float* __restrict__ Wih, const float* __restrict__ Whh) {
    int idx = blockIdx.x * blockDim.x + threadIdx.x;
    if (idx >= 4 * H * KP) return;
    int g = idx / (H * KP);
    int r = idx % (H * KP);
    int j = r / KP, k = r % KP;
    float v;
    if (k < H) {
        if (g == 0)      v = Whh[(size_t)j * H + k]           - Wih[(size_t)j * H + k];
        else if (g == 1) v = Whh[(size_t)(H + j) * H + k]     - Wih[(size_t)(H + j) * H + k];
        else if (g == 2) v = Whh[(size_t)(2 * H + j) * H + k];
        else             v = -Wih[(size_t)(2 * H + j) * H + k];
    } else {
        int d = k - H;
        if (g == 2) v = 0.f;
        else {
            size_t base = (size_t)((g == 0) ? j : (g == 1) ? (H + j) : (2 * H + j)) * H;
            v = 0.f;
            #pragma unroll
            for (int c = 0; c < 5; c++) v += Wih[base + c * NI + d];
        }
    }
    g_WB[idx] = tf32r(v);
}

// ---------------- embedding gather (+ S columns) into g_A0 ----------------
__global__ void gather_kernel(const int* __restrict__ feat,
                              const float* __restrict__ e0, const float* __restrict__ e1,
                              const float* __restrict__ e2, const float* __restrict__ e3,
                              const float* __restrict__ e4) {
    int i = blockIdx.x * blockDim.x + threadIdx.x;
    int row = i >> 7, d = i & 127;
    const int* f = feat + row * 5;
    float v0 = e0[(size_t)f[0] * NI + d];
    float v1 = e1[(size_t)f[1] * NI + d];
    float v2 = e2[(size_t)f[2] * NI + d];
    float v3 = e3[(size_t)f[3] * NI + d];
    float v4 = e4[(size_t)f[4] * NI + d];
    float* ar = g_A0 + (size_t)row * KP;
    ar[0 * NI + d] = tf32r(v0);
    ar[1 * NI + d] = tf32r(v1);
    ar[2 * NI + d] = tf32r(v2);
    ar[3 * NI + d] = tf32r(v3);
    ar[4 * NI + d] = tf32r(v4);
    ar[H + d]      = tf32r(v0 + v1 + v2 + v3 + v4);
}

// fill S columns of A from its h columns (between rounds)
__global__ void sum_kernel(float* __restrict__ A) {
    int i = blockIdx.x * blockDim.x + threadIdx.x;
    int row = i >> 7, d = i & 127;
    float* ar = A + (size_t)row * KP;
    ar[H + d] = tf32r(ar[d] + ar[NI + d] + ar[2 * NI + d] + ar[3 * NI + d] + ar[4 * NI + d]);
}

// ---------------- fused GRU round: tf32 mma.sync GEMM + gate epilogue ----------------
// CTA: 128 (M) x 32 (N), 8 warps = 4(M) x 2(N); warp tile 32x16 per gate, 4 gates.
// K = 768 in 24 chunks of 32; cp.async double-buffered smem, pad 36 (conflict-free frags).
__global__ __launch_bounds__(256, 2)
void gru_mma(const float* __restrict__ Ain, float* __restrict__ Aout,
             const float* __restrict__ bih, const float* __restrict__ bhh) {
    extern __shared__ float smem[];
    float* As = smem;               // [2][128][36]
    float* Bsm = smem + 2 * 128 * 36; // [2][4*32][36]

    const int tid = threadIdx.x, lane = tid & 31, wid = tid >> 5;
    const int g = lane >> 2, t = lane & 3;
    const int wm = wid >> 1, wn = wid & 1;
    const int row0 = blockIdx.y * 128;
    const int j0 = blockIdx.x * 32;
    const int lr = tid >> 3, lq = tid & 7;   // loader: 32 rows x 8 quads per 256-thread pass

    float acc[4][16];
    #pragma unroll
    for (int a = 0; a < 4; a++)
        #pragma unroll
        for (int q = 0; q < 16; q++) acc[a][q] = 0.f;

    const float* Abase = Ain + (size_t)row0 * KP;

    // issue chunk c into stage s
    auto issue = [&](int c, int s) {
        int kc = c * 32;
        float* Asd = As + s * 4608;
        #pragma unroll
        for (int it = 0; it < 4; it++) {
            int r = it * 32 + lr;
            uint32_t d = (uint32_t)__cvta_generic_to_shared(Asd + r * 36 + lq * 4);
            CP_ASYNC16(d, Abase + (size_t)r * KP + kc + lq * 4);
        }
        float* Bsd = Bsm + s * 4608;
        #pragma unroll
        for (int it = 0; it < 4; it++) {   // it == gate
            uint32_t d = (uint32_t)__cvta_generic_to_shared(Bsd + (it * 32 + lr) * 36 + lq * 4);
            CP_ASYNC16(d, g_WB + ((size_t)it * H + j0 + lr) * KP + kc + lq * 4);
        }
        CP_COMMIT();
    };

    issue(0, 0);
    const int NCH = KP / 32;  // 24
    for (int c = 0; c < NCH; c++) {
        if (c < NCH - 1) { issue(c + 1, (c + 1) & 1); CP_WAIT1(); }
        else             { CP_WAIT0(); }
        __syncthreads();

        const uint32_t* Au = (const uint32_t*)(As + (c & 1) * 4608);
        const uint32_t* Bu = (const uint32_t*)(Bsm + (c & 1) * 4608);
        #pragma unroll
        for (int kk = 0; kk < 32; kk += 8) {
            uint32_t afr[2][4];
            #pragma unroll
            for (int mt = 0; mt < 2; mt++) {
                int r = wm * 32 + mt * 16 + g;
                afr[mt][0] = Au[r * 36 + kk + t];
                afr[mt][1] = Au[(r + 8) * 36 + kk + t];
                afr[mt][2] = Au[r * 36 + kk + t + 4];
                afr[mt][3] = Au[(r + 8) * 36 + kk + t + 4];
            }
            uint32_t bfr[4][2][2];
            #pragma unroll
            for (int ga = 0; ga < 4; ga++)
                #pragma unroll
                for (int nt = 0; nt < 2; nt++) {
                    int n = ga * 32 + wn * 16 + nt * 8 + g;
                    bfr[ga][nt][0] = Bu[n * 36 + kk + t];
                    bfr[ga][nt][1] = Bu[n * 36 + kk + t + 4];
                }
            #pragma unroll
            for (int ga = 0; ga < 4; ga++)
                #pragma unroll
                for (int mt = 0; mt < 2; mt++)
                    #pragma unroll
                    for (int nt = 0; nt < 2; nt++)
                        mma_tf32(&acc[ga][mt * 8 + nt * 4], afr[mt], bfr[ga][nt]);
        }
        __syncthreads();
    }

    // ---- fused GRU gate epilogue ----
    #pragma unroll
    for (int nt = 0; nt < 2; nt++)
        #pragma unroll
        for (int ct = 0; ct < 2; ct++) {
            int j = j0 + wn * 16 + nt * 8 + 2 * t + ct;
            float brb  = bih[j] + bhh[j];
            float bzb  = bih[H + j] + bhh[H + j];
            float bnbi = bih[2 * H + j];
            float bnbh = bhh[2 * H + j];
            #pragma unroll
            for (int mt = 0; mt < 2; mt++)
                #pragma unroll
                for (int rh = 0; rh < 2; rh++) {
                    int m = row0 + wm * 32 + mt * 16 + g + 8 * rh;
                    int ci = mt * 8 + nt * 4 + rh * 2 + ct;
                    float r = 1.f / (1.f + expf(-(acc[0][ci] + brb)));
                    float z = 1.f / (1.f + expf(-(acc[1][ci] + bzb)));
                    float n = tanhf(acc[3][ci] + bnbi + r * (acc[2][ci] + bnbh));
                    float hp = Ain[(size_t)m * KP + j];
                    Aout[(size_t)m * KP + j] = tf32r((1.f - z) * n + z * hp);
                }
        }
}

// ---------------- final FC (fp32 SIMT): out = h @ Wfc^T + bfc ----------------
#define TM 64
#define TN 64
#define BK 16
__global__ __launch_bounds__(256, 2)
void fc_kernel(const float* __restrict__ Wfc, const float* __restrict__ bfc,
               float* __restrict__ out) {
    __shared__ __align__(16) float Asx[BK][TM + 4];
    __shared__ __align__(16) float Bsx[BK][TN + 4];

    int tid = threadIdx.x;
    int tx = tid & 15, ty = tid >> 4;
    int lm = tid >> 2, lq = tid & 3;
    int row0 = blockIdx.x * TM;
    int j0 = blockIdx.y * TN;

    float acc[16];
    #pragma unroll
    for (int q = 0; q < 16; q++) acc[q] = 0.f;

    for (int k0 = 0; k0 < H; k0 += BK) {
        float4 v;
        v = *(const float4*)&g_A0[(size_t)(row0 + lm) * KP + k0 + lq * 4];
        Asx[lq*4+0][lm] = v.x; Asx[lq*4+1][lm] = v.y; Asx[lq*4+2][lm] = v.z; Asx[lq*4+3][lm] = v.w;
        v = *(const float4*)&Wfc[(size_t)(j0 + lm) * H + k0 + lq * 4];
        Bsx[lq*4+0][lm] = v.x; Bsx[lq*4+1][lm] = v.y; Bsx[lq*4+2][lm] = v.z; Bsx[lq*4+3][lm] = v.w;
        __syncthreads();

        #pragma unroll
        for (int k = 0; k < BK; k++) {
            float4 a = *(float4*)&Asx[k][ty * 4];
            float4 b = *(float4*)&Bsx[k][tx * 4];
            float av[4] = {a.x, a.y, a.z, a.w};
            float bv[4] = {b.x, b.y, b.z, b.w};
            #pragma unroll
            for (int i = 0; i < 4; i++)
                #pragma unroll
                for (int jj = 0; jj < 4; jj++)
                    acc[i*4+jj] += av[i] * bv[jj];
        }
        __syncthreads();
    }

    int mbase = row0 + ty * 4;
    #pragma unroll
    for (int jj = 0; jj < 4; jj++) {
        int j = j0 + tx * 4 + jj;
        float bb = bfc[j];
        #pragma unroll
        for (int i = 0; i < 4; i++)
            out[(size_t)(mbase + i) * NO + j] = acc[i*4+jj] + bb;
    }
}

// ---------------- launch ----------------
extern "C" void kernel_launch(void* const* d_in, const int* in_sizes, int n_in,
                              void* d_out, int out_size) {
    const int*   feat = (const int*)  d_in[0];
    const float* e_id = (const float*)d_in[1];
    const float* e_ag = (const float*)d_in[2];
    const float* e_ge = (const float*)d_in[3];
    const float* e_oc = (const float*)d_in[4];
    const float* e_zp = (const float*)d_in[5];
    const float* Wih  = (const float*)d_in[6];
    const float* Whh  = (const float*)d_in[7];
    const float* bih  = (const float*)d_in[8];
    const float* bhh  = (const float*)d_in[9];
    const float* Wfc  = (const float*)d_in[10];
    const float* bfc  = (const float*)d_in[11];
    float* out = (float*)d_out;

    const int smem_bytes = 2 * (128 * 36 + 4 * 32 * 36) * 4;  // 73728
    cudaFuncSetAttribute(gru_mma, cudaFuncAttributeMaxDynamicSharedMemorySize, smem_bytes);

    prep_wb<<<(4 * H * KP + 255) / 256, 256>>>(Wih, Whh);
    gather_kernel<<<(BS * NI) / 256, 256>>>(feat, e_id, e_ag, e_ge, e_oc, e_zp);

    float* A0;  cudaGetSymbolAddress((void**)&A0, g_A0);
    float* A1;  cudaGetSymbolAddress((void**)&A1, g_A1);

    dim3 gg(H / 32, BS / 128);   // x = N blocks (20), y = M blocks (256) -> A reuse in L2
    gru_mma<<<gg, 256, smem_bytes>>>(A0, A1, bih, bhh);   // round 1: A0 -> A1
    sum_kernel<<<(BS * NI) / 256, 256>>>(A1);
    gru_mma<<<gg, 256, smem_bytes>>>(A1, A0, bih, bhh);   // round 2: A1 -> A0

    dim3 gf(BS / TM, NO / TN);
    fc_kernel<<<gf, 256>>>(Wfc, bfc, out);
}

// round 5
// speedup vs baseline: 5.8361x; 2.0413x over previous
#include <cuda_runtime.h>
#include <cuda_fp16.h>
#include <math.h>
#include <stdint.h>

#define BS 32768
#define NI 128
#define H  640
#define H3 1920
#define NO 256
#define KP 768          // packed K: 640 (h) + 128 (S)

// ---------------- scratch (device globals) ----------------
__device__ __half g_A0[BS * KP];           // 50 MB: [h | S] fp16
__device__ __half g_A1[BS * KP];           // 50 MB
__device__ __half g_WB[4 * H * KP];        // 3.9 MB: packed per-gate weights fp16
__device__ __half g_Wfch[NO * H];          // FC weight fp16

__device__ __forceinline__ void mma_f16(float* c, const uint32_t* a, const uint32_t* b) {
    asm volatile(
        "mma.sync.aligned.m16n8k16.row.col.f32.f16.f16.f32 "
        "{%0,%1,%2,%3}, {%4,%5,%6,%7}, {%8,%9}, {%0,%1,%2,%3};"
        : "+f"(c[0]), "+f"(c[1]), "+f"(c[2]), "+f"(c[3])
        : "r"(a[0]), "r"(a[1]), "r"(a[2]), "r"(a[3]), "r"(b[0]), "r"(b[1]));
}

#define CP_ASYNC16(dst_u32, src_ptr) \
    asm volatile("cp.async.cg.shared.global [%0], [%1], 16;\n" :: "r"(dst_u32), "l"(src_ptr))
#define CP_COMMIT() asm volatile("cp.async.commit_group;\n" ::)
#define CP_WAIT1()  asm volatile("cp.async.wait_group 1;\n" ::)
#define CP_WAIT0()  asm volatile("cp.async.wait_group 0;\n" ::)

// ---------------- weight packing ----------------
// g_WB[g][j][k]: g0: Whh_r - Wih_r ; g1: Whh_z - Wih_z ; g2: Whh_n ; g3: -Wih_n
// k >= 640 (d = k-640): folded S columns (sum over 5 nodes of Wih); 0 for g2.
__global__ void prep_wb(const float* __restrict__ Wih, const float* __restrict__ Whh) {
    int idx = blockIdx.x * blockDim.x + threadIdx.x;
    if (idx >= 4 * H * KP) return;
    int g = idx / (H * KP);
    int r = idx % (H * KP);
    int j = r / KP, k = r % KP;
    float v;
    if (k < H) {
        if (g == 0)      v = Whh[(size_t)j * H + k]           - Wih[(size_t)j * H + k];
        else if (g == 1) v = Whh[(size_t)(H + j) * H + k]     - Wih[(size_t)(H + j) * H + k];
        else if (g == 2) v = Whh[(size_t)(2 * H + j) * H + k];
        else             v = -Wih[(size_t)(2 * H + j) * H + k];
    } else {
        int d = k - H;
        if (g == 2) v = 0.f;
        else {
            size_t base = (size_t)((g == 0) ? j : (g == 1) ? (H + j) : (2 * H + j)) * H;
            v = 0.f;
            #pragma unroll
            for (int c = 0; c < 5; c++) v += Wih[base + c * NI + d];
        }
    }
    g_WB[idx] = __float2half_rn(v);
}

__global__ void prep_wfc(const float* __restrict__ Wfc) {
    int i = blockIdx.x * blockDim.x + threadIdx.x;
    if (i < NO * H) g_Wfch[i] = __float2half_rn(Wfc[i]);
}

// ---------------- embedding gather (+ S columns) into g_A0 ----------------
__global__ void gather_kernel(const int* __restrict__ feat,
                              const float* __restrict__ e0, const float* __restrict__ e1,
                              const float* __restrict__ e2, const float* __restrict__ e3,
                              const float* __restrict__ e4) {
    int i = blockIdx.x * blockDim.x + threadIdx.x;
    int row = i >> 7, d = i & 127;
    const int* f = feat + row * 5;
    float v0 = e0[(size_t)f[0] * NI + d];
    float v1 = e1[(size_t)f[1] * NI + d];
    float v2 = e2[(size_t)f[2] * NI + d];
    float v3 = e3[(size_t)f[3] * NI + d];
    float v4 = e4[(size_t)f[4] * NI + d];
    __half* ar = g_A0 + (size_t)row * KP;
    ar[0 * NI + d] = __float2half_rn(v0);
    ar[1 * NI + d] = __float2half_rn(v1);
    ar[2 * NI + d] = __float2half_rn(v2);
    ar[3 * NI + d] = __float2half_rn(v3);
    ar[4 * NI + d] = __float2half_rn(v4);
    ar[H + d]      = __float2half_rn(v0 + v1 + v2 + v3 + v4);
}

// fill S columns of A from its h columns (between rounds)
__global__ void sum_kernel(__half* __restrict__ A) {
    int i = blockIdx.x * blockDim.x + threadIdx.x;
    int row = i >> 7, d = i & 127;
    __half* ar = A + (size_t)row * KP;
    float s = __half2float(ar[d]) + __half2float(ar[NI + d]) + __half2float(ar[2 * NI + d])
            + __half2float(ar[3 * NI + d]) + __half2float(ar[4 * NI + d]);
    ar[H + d] = __float2half_rn(s);
}

// ---------------- fused GRU round: fp16 mma.sync GEMM + gate epilogue ----------------
// CTA: 128 (M) x 32 (N) per gate, 4 gates; 8 warps = 4(M) x 2(N); warp 32x16 per gate.
// K = 768 in 12 chunks of 64 halves (128 B/row); cp.async double-buffered smem.
// Smem rows padded to 72 halves (36 u32) -> conflict-free fragment LDS.
__global__ __launch_bounds__(256, 2)
void gru_mma(const __half* __restrict__ Ain, __half* __restrict__ Aout,
             const float* __restrict__ bih, const float* __restrict__ bhh) {
    extern __shared__ __half smem[];
    __half* As  = smem;                 // [2][128][72]
    __half* Bsm = smem + 2 * 128 * 72;  // [2][4*32][72]

    const int tid = threadIdx.x, lane = tid & 31, wid = tid >> 5;
    const int g = lane >> 2, t = lane & 3;
    const int wm = wid >> 1, wn = wid & 1;
    const int row0 = blockIdx.y * 128;
    const int j0 = blockIdx.x * 32;
    const int lr = tid >> 3, lq = tid & 7;   // loader: 32 rows x 8 16B-quads

    float acc[4][16];
    #pragma unroll
    for (int a = 0; a < 4; a++)
        #pragma unroll
        for (int q = 0; q < 16; q++) acc[a][q] = 0.f;

    const __half* Abase = Ain + (size_t)row0 * KP;

    auto issue = [&](int c, int s) {
        int kc = c * 64;                       // halves
        __half* Asd = As + s * (128 * 72);
        #pragma unroll
        for (int it = 0; it < 4; it++) {
            int r = it * 32 + lr;
            uint32_t d = (uint32_t)__cvta_generic_to_shared(Asd + r * 72 + lq * 8);
            CP_ASYNC16(d, Abase + (size_t)r * KP + kc + lq * 8);
        }
        __half* Bsd = Bsm + s * (128 * 72);
        #pragma unroll
        for (int it = 0; it < 4; it++) {       // it == gate
            uint32_t d = (uint32_t)__cvta_generic_to_shared(Bsd + (it * 32 + lr) * 72 + lq * 8);
            CP_ASYNC16(d, g_WB + ((size_t)it * H + j0 + lr) * KP + kc + lq * 8);
        }
        CP_COMMIT();
    };

    issue(0, 0);
    const int NCH = KP / 64;  // 12
    for (int c = 0; c < NCH; c++) {
        if (c < NCH - 1) { issue(c + 1, (c + 1) & 1); CP_WAIT1(); }
        else             { CP_WAIT0(); }
        __syncthreads();

        const uint32_t* Au = (const uint32_t*)(As + (c & 1) * (128 * 72));
        const uint32_t* Bu = (const uint32_t*)(Bsm + (c & 1) * (128 * 72));
        #pragma unroll
        for (int ks = 0; ks < 4; ks++) {       // 4 k16 steps per 64-half chunk
            int kk2 = ks * 8;                  // u32 offset
            uint32_t afr[2][4];
            #pragma unroll
            for (int mt = 0; mt < 2; mt++) {
                int r = wm * 32 + mt * 16 + g;
                afr[mt][0] = Au[r * 36 + kk2 + t];
                afr[mt][1] = Au[(r + 8) * 36 + kk2 + t];
                afr[mt][2] = Au[r * 36 + kk2 + 4 + t];
                afr[mt][3] = Au[(r + 8) * 36 + kk2 + 4 + t];
            }
            uint32_t bfr[4][2][2];
            #pragma unroll
            for (int ga = 0; ga < 4; ga++)
                #pragma unroll
                for (int nt = 0; nt < 2; nt++) {
                    int n = ga * 32 + wn * 16 + nt * 8 + g;
                    bfr[ga][nt][0] = Bu[n * 36 + kk2 + t];
                    bfr[ga][nt][1] = Bu[n * 36 + kk2 + 4 + t];
                }
            #pragma unroll
            for (int ga = 0; ga < 4; ga++)
                #pragma unroll
                for (int mt = 0; mt < 2; mt++)
                    #pragma unroll
                    for (int nt = 0; nt < 2; nt++)
                        mma_f16(&acc[ga][mt * 8 + nt * 4], afr[mt], bfr[ga][nt]);
        }
        __syncthreads();
    }

    // ---- fused GRU gate epilogue ----
    #pragma unroll
    for (int nt = 0; nt < 2; nt++)
        #pragma unroll
        for (int ct = 0; ct < 2; ct++) {
            int j = j0 + wn * 16 + nt * 8 + 2 * t + ct;
            float brb  = bih[j] + bhh[j];
            float bzb  = bih[H + j] + bhh[H + j];
            float bnbi = bih[2 * H + j];
            float bnbh = bhh[2 * H + j];
            #pragma unroll
            for (int mt = 0; mt < 2; mt++)
                #pragma unroll
                for (int rh = 0; rh < 2; rh++) {
                    int m = row0 + wm * 32 + mt * 16 + g + 8 * rh;
                    int ci = mt * 8 + nt * 4 + rh * 2 + ct;
                    float r = 1.f / (1.f + expf(-(acc[0][ci] + brb)));
                    float z = 1.f / (1.f + expf(-(acc[1][ci] + bzb)));
                    float n = tanhf(acc[3][ci] + bnbi + r * (acc[2][ci] + bnbh));
                    float hp = __half2float(Ain[(size_t)m * KP + j]);
                    Aout[(size_t)m * KP + j] = __float2half_rn((1.f - z) * n + z * hp);
                }
        }
}

// ---------------- final FC via fp16 mma: out = h @ Wfc^T + bfc ----------------
// CTA 128(M) x 64(N), K = 640 in 10 chunks of 64 halves. Warp 32x32 (mt2 x nt4).
__global__ __launch_bounds__(256, 2)
void fc_mma(const __half* __restrict__ Ain, const float* __restrict__ bfc,
            float* __restrict__ out) {
    extern __shared__ __half smem[];
    __half* As  = smem;                 // [2][128][72]
    __half* Bsm = smem + 2 * 128 * 72;  // [2][64][72]

    const int tid = threadIdx.x, lane = tid & 31, wid = tid >> 5;
    const int g = lane >> 2, t = lane & 3;
    const int wm = wid >> 1, wn = wid & 1;
    const int row0 = blockIdx.y * 128;
    const int j0 = blockIdx.x * 64;
    const int lr = tid >> 3, lq = tid & 7;

    float acc[2][4][4];
    #pragma unroll
    for (int a = 0; a < 2; a++)
        #pragma unroll
        for (int b = 0; b < 4; b++)
            #pragma unroll
            for (int q = 0; q < 4; q++) acc[a][b][q] = 0.f;

    const __half* Abase = Ain + (size_t)row0 * KP;

    auto issue = [&](int c, int s) {
        int kc = c * 64;
        __half* Asd = As + s * (128 * 72);
        #pragma unroll
        for (int it = 0; it < 4; it++) {
            int r = it * 32 + lr;
            uint32_t d = (uint32_t)__cvta_generic_to_shared(Asd + r * 72 + lq * 8);
            CP_ASYNC16(d, Abase + (size_t)r * KP + kc + lq * 8);
        }
        __half* Bsd = Bsm + s * (64 * 72);
        #pragma unroll
        for (int it = 0; it < 2; it++) {
            int n = it * 32 + lr;
            uint32_t d = (uint32_t)__cvta_generic_to_shared(Bsd + n * 72 + lq * 8);
            CP_ASYNC16(d, g_Wfch + (size_t)(j0 + n) * H + kc + lq * 8);
        }
        CP_COMMIT();
    };

    issue(0, 0);
    const int NCH = H / 64;  // 10
    for (int c = 0; c < NCH; c++) {
        if (c < NCH - 1) { issue(c + 1, (c + 1) & 1); CP_WAIT1(); }
        else             { CP_WAIT0(); }
        __syncthreads();

        const uint32_t* Au = (const uint32_t*)(As + (c & 1) * (128 * 72));
        const uint32_t* Bu = (const uint32_t*)(Bsm + (c & 1) * (64 * 72));
        #pragma unroll
        for (int ks = 0; ks < 4; ks++) {
            int kk2 = ks * 8;
            uint32_t afr[2][4];
            #pragma unroll
            for (int mt = 0; mt < 2; mt++) {
                int r = wm * 32 + mt * 16 + g;
                afr[mt][0] = Au[r * 36 + kk2 + t];
                afr[mt][1] = Au[(r + 8) * 36 + kk2 + t];
                afr[mt][2] = Au[r * 36 + kk2 + 4 + t];
                afr[mt][3] = Au[(r + 8) * 36 + kk2 + 4 + t];
            }
            uint32_t bfr[4][2];
            #pragma unroll
            for (int nt = 0; nt < 4; nt++) {
                int n = wn * 32 + nt * 8 + g;
                bfr[nt][0] = Bu[n * 36 + kk2 + t];
                bfr[nt][1] = Bu[n * 36 + kk2 + 4 + t];
            }
            #pragma unroll
            for (int mt = 0; mt < 2; mt++)
                #pragma unroll
                for (int nt = 0; nt < 4; nt++)
                    mma_f16(acc[mt][nt], afr[mt], bfr[nt]);
        }
        __syncthreads();
    }

    #pragma unroll
    for (int nt = 0; nt < 4; nt++)
        #pragma unroll
        for (int ct = 0; ct < 2; ct++) {
            int j = j0 + wn * 32 + nt * 8 + 2 * t + ct;
            float bb = bfc[j];
            #pragma unroll
            for (int mt = 0; mt < 2; mt++)
                #pragma unroll
                for (int rh = 0; rh < 2; rh++) {
                    int m = row0 + wm * 32 + mt * 16 + g + 8 * rh;
                    out[(size_t)m * NO + j] = acc[mt][nt][rh * 2 + ct] + bb;
                }
        }
}

// ---------------- launch ----------------
extern "C" void kernel_launch(void* const* d_in, const int* in_sizes, int n_in,
                              void* d_out, int out_size) {
    const int*   feat = (const int*)  d_in[0];
    const float* e_id = (const float*)d_in[1];
    const float* e_ag = (const float*)d_in[2];
    const float* e_ge = (const float*)d_in[3];
    const float* e_oc = (const float*)d_in[4];
    const float* e_zp = (const float*)d_in[5];
    const float* Wih  = (const float*)d_in[6];
    const float* Whh  = (const float*)d_in[7];
    const float* bih  = (const float*)d_in[8];
    const float* bhh  = (const float*)d_in[9];
    const float* Wfc  = (const float*)d_in[10];
    const float* bfc  = (const float*)d_in[11];
    float* out = (float*)d_out;

    const int smem_gru = 2 * (128 * 72 + 128 * 72) * 2;  // 73728 B
    const int smem_fc  = 2 * (128 * 72 + 64 * 72) * 2;   // 55296 B
    cudaFuncSetAttribute(gru_mma, cudaFuncAttributeMaxDynamicSharedMemorySize, smem_gru);
    cudaFuncSetAttribute(fc_mma,  cudaFuncAttributeMaxDynamicSharedMemorySize, smem_fc);

    prep_wb<<<(4 * H * KP + 255) / 256, 256>>>(Wih, Whh);
    prep_wfc<<<(NO * H + 255) / 256, 256>>>(Wfc);
    gather_kernel<<<(BS * NI) / 256, 256>>>(feat, e_id, e_ag, e_ge, e_oc, e_zp);

    __half* A0;  cudaGetSymbolAddress((void**)&A0, g_A0);
    __half* A1;  cudaGetSymbolAddress((void**)&A1, g_A1);

    dim3 gg(H / 32, BS / 128);   // 20 x 256
    gru_mma<<<gg, 256, smem_gru>>>(A0, A1, bih, bhh);   // round 1: A0 -> A1
    sum_kernel<<<(BS * NI) / 256, 256>>>(A1);
    gru_mma<<<gg, 256, smem_gru>>>(A1, A0, bih, bhh);   // round 2: A1 -> A0

    dim3 gf(NO / 64, BS / 128);  // 4 x 256
    fc_mma<<<gf, 256, smem_fc>>>(A0, bfc, out);
}